// round 16
// baseline (speedup 1.0000x reference)
#include <cuda_runtime.h>
#include <cuda_bf16.h>
#include <cstdint>

// ---------------- problem dims ----------------
#define B_   2
#define T_   2048
#define HID  2048
#define NH   6
#define DK   256
#define DV   512
#define KD   1536      // NH*DK
#define VD   3072      // NH*DV
#define BT   4096      // B_*T_
#define CK   4

// fused projection layout: [q(1536) | k(1536) | v(3072) | g(3072)]
#define PST  9216
#define QOFF 0
#define KOFF 1536
#define VOFF 3072
#define GOFF 6144

typedef unsigned long long ull;

// ---------------- scratch (device globals; no allocs allowed) ----------------
__device__ float d_P[(size_t)BT * PST];       // fused projection output (fp32)
__device__ float d_Qc[BT * KD];
__device__ float d_Kc[BT * KD];
__device__ float d_Vc[(size_t)BT * VD];
__device__ float d_EG[BT * NH];
__device__ float d_Beta[BT * NH];
__device__ float d_O[(size_t)BT * VD];

// bf16 split operand buffers
__device__ __nv_bfloat16 d_Hh[(size_t)BT * HID];
__device__ __nv_bfloat16 d_Hl[(size_t)BT * HID];
__device__ __nv_bfloat16 d_Wbh[(size_t)HID * PST];   // [Wq|Wk|Wv|Wg] hi
__device__ __nv_bfloat16 d_Wbl[(size_t)HID * PST];   // lo
__device__ __nv_bfloat16 d_Woh[(size_t)VD * HID];
__device__ __nv_bfloat16 d_Wol[(size_t)VD * HID];
__device__ __nv_bfloat16 d_Gh[(size_t)BT * VD];
__device__ __nv_bfloat16 d_Gl[(size_t)BT * VD];

// ---------------- packed f32x2 helpers (recurrence) ----------------
__device__ __forceinline__ ull fma2(ull a, ull b, ull c) {
    ull d;
    asm("fma.rn.f32x2 %0, %1, %2, %3;" : "=l"(d) : "l"(a), "l"(b), "l"(c));
    return d;
}
__device__ __forceinline__ ull mul2(ull a, ull b) {
    ull d;
    asm("mul.rn.f32x2 %0, %1, %2;" : "=l"(d) : "l"(a), "l"(b));
    return d;
}
__device__ __forceinline__ ull add2(ull a, ull b) {
    ull d;
    asm("add.rn.f32x2 %0, %1, %2;" : "=l"(d) : "l"(a), "l"(b));
    return d;
}
__device__ __forceinline__ ull pack2(float lo, float hi) {
    ull d;
    asm("mov.b64 %0, {%1, %2};" : "=l"(d) : "f"(lo), "f"(hi));
    return d;
}
__device__ __forceinline__ void unpack2(ull v, float& lo, float& hi) {
    asm("mov.b64 {%0, %1}, %2;" : "=f"(lo), "=f"(hi) : "l"(v));
}
__device__ __forceinline__ float sigm(float x) { return 1.0f / (1.0f + __expf(-x)); }

// ---------------- mma.sync bf16 GEMM machinery ----------------
__device__ __forceinline__ uint32_t smem_u32(const void* p) {
    uint32_t a;
    asm("{ .reg .u64 t; cvta.to.shared.u64 t, %1; cvt.u32.u64 %0, t; }" : "=r"(a) : "l"(p));
    return a;
}
__device__ __forceinline__ uint32_t pkbf(float x, float y) {
    uint32_t r;
    asm("cvt.rn.bf16x2.f32 %0, %1, %2;" : "=r"(r) : "f"(y), "f"(x));
    return r;
}
__device__ __forceinline__ void ldsm_x4(uint32_t* r, uint32_t a) {
    asm volatile("ldmatrix.sync.aligned.m8n8.x4.shared.b16 {%0,%1,%2,%3}, [%4];"
                 : "=r"(r[0]), "=r"(r[1]), "=r"(r[2]), "=r"(r[3]) : "r"(a));
}
__device__ __forceinline__ void ldsm_x4_t(uint32_t* r, uint32_t a) {
    asm volatile("ldmatrix.sync.aligned.m8n8.x4.trans.shared.b16 {%0,%1,%2,%3}, [%4];"
                 : "=r"(r[0]), "=r"(r[1]), "=r"(r[2]), "=r"(r[3]) : "r"(a));
}
__device__ __forceinline__ void mma_bf16(float* d, const uint32_t* a, const uint32_t* b) {
    asm volatile(
        "mma.sync.aligned.m16n8k16.row.col.f32.bf16.bf16.f32 "
        "{%0,%1,%2,%3}, {%4,%5,%6,%7}, {%8,%9}, {%0,%1,%2,%3};"
        : "+f"(d[0]), "+f"(d[1]), "+f"(d[2]), "+f"(d[3])
        : "r"(a[0]), "r"(a[1]), "r"(a[2]), "r"(a[3]), "r"(b[0]), "r"(b[1]));
}
__device__ __forceinline__ void cpa16(uint32_t dst, const void* src) {
    asm volatile("cp.async.cg.shared.global [%0], [%1], 16;" :: "r"(dst), "l"(src));
}
__device__ __forceinline__ void cpa4(uint32_t dst, const void* src) {
    asm volatile("cp.async.ca.shared.global [%0], [%1], 4;" :: "r"(dst), "l"(src));
}
#define CP_COMMIT() asm volatile("cp.async.commit_group;" ::: "memory")
#define CP_WAIT1()  asm volatile("cp.async.wait_group 1;" ::: "memory")
#define CP_WAIT2()  asm volatile("cp.async.wait_group 2;" ::: "memory")

// tiles: 128(M) x 64(N), BK=32, 3 stages, 2 CTAs/SM
#define BM 128
#define BN 64
#define BKf 32
#define STAGES 3
#define A_STR 80
#define B_STR 144
#define AT_BYTES (128 * A_STR)
#define BTI_BYTES (32 * B_STR)
#define OFF_AH 0
#define OFF_AL AT_BYTES
#define OFF_BH (2 * AT_BYTES)
#define OFF_BL (2 * AT_BYTES + BTI_BYTES)
#define STAGE_BYTES (2 * AT_BYTES + 2 * BTI_BYTES)
#define SMEM_GB (STAGES * STAGE_BYTES)

__device__ __forceinline__ void g_issue(uint32_t st,
                                        const __nv_bfloat16* __restrict__ Ah,
                                        const __nv_bfloat16* __restrict__ Al,
                                        const __nv_bfloat16* __restrict__ Bh,
                                        const __nv_bfloat16* __restrict__ Bl,
                                        int m0, int n0, int kt, int K, int N, int tid) {
#pragma unroll
    for (int half = 0; half < 2; half++) {
        int r = (tid >> 2) + half * 64;
        int ke = (tid & 3) * 8;
        const size_t ga = (size_t)(m0 + r) * K + kt * BKf + ke;
        uint32_t so = st + r * A_STR + ke * 2;
        cpa16(so + OFF_AH, Ah + ga);
        cpa16(so + OFF_AL, Al + ga);
    }
    {
        int r = tid >> 3;
        int ke = (tid & 7) * 8;
        const size_t gb = (size_t)(kt * BKf + r) * N + n0 + ke;
        uint32_t so = st + r * B_STR + ke * 2;
        cpa16(so + OFF_BH, Bh + gb);
        cpa16(so + OFF_BL, Bl + gb);
    }
}

__device__ __forceinline__ void g_compute(uint32_t st, int wid, int lane, float (*acc)[4][4]) {
    const int wm = (wid & 3) * 32, wn = (wid >> 2) * 32;
    const int arow = lane & 15;
    const int acg = (lane >> 4) * 8;
    const int brow = (lane & 7) + ((lane >> 3) & 1) * 8;
    const int bcg = (lane >> 4) * 8;
#pragma unroll
    for (int ks = 0; ks < BKf; ks += 16) {
        uint32_t ah[2][4], al[2][4], bh[2][4], bl[2][4];
#pragma unroll
        for (int mt = 0; mt < 2; mt++) {
            uint32_t ad = st + OFF_AH + (wm + mt * 16 + arow) * A_STR + (ks + acg) * 2;
            ldsm_x4(ah[mt], ad);
            ldsm_x4(al[mt], ad + (OFF_AL - OFF_AH));
        }
#pragma unroll
        for (int nt = 0; nt < 2; nt++) {
            uint32_t bd = st + OFF_BH + (ks + brow) * B_STR + (wn + nt * 16 + bcg) * 2;
            ldsm_x4_t(bh[nt], bd);
            ldsm_x4_t(bl[nt], bd + (OFF_BL - OFF_BH));
        }
#pragma unroll
        for (int mt = 0; mt < 2; mt++)
#pragma unroll
            for (int j = 0; j < 4; j++)
                mma_bf16(acc[mt][j], ah[mt], &bh[j >> 1][(j & 1) * 2]);
#pragma unroll
        for (int mt = 0; mt < 2; mt++)
#pragma unroll
            for (int j = 0; j < 4; j++)
                mma_bf16(acc[mt][j], ah[mt], &bl[j >> 1][(j & 1) * 2]);
#pragma unroll
        for (int mt = 0; mt < 2; mt++)
#pragma unroll
            for (int j = 0; j < 4; j++)
                mma_bf16(acc[mt][j], al[mt], &bh[j >> 1][(j & 1) * 2]);
    }
}

// C[M,N] = A[M,K] @ B[K,N]; operands pre-split hi/lo bf16, fp32 out
__global__ __launch_bounds__(256, 2) void gemm_bf(const __nv_bfloat16* __restrict__ Ah,
                                                  const __nv_bfloat16* __restrict__ Al,
                                                  const __nv_bfloat16* __restrict__ Bh,
                                                  const __nv_bfloat16* __restrict__ Bl,
                                                  float* __restrict__ C,
                                                  int M, int N, int K) {
    extern __shared__ char smem[];
    const uint32_t sb = smem_u32(smem);
    const int tid = threadIdx.x, lane = tid & 31, wid = tid >> 5;
    const int m0 = blockIdx.y * BM, n0 = blockIdx.x * BN;
    const int NT = K / BKf;

    float acc[2][4][4];
#pragma unroll
    for (int mt = 0; mt < 2; mt++)
#pragma unroll
        for (int j = 0; j < 4; j++)
#pragma unroll
            for (int p = 0; p < 4; p++) acc[mt][j][p] = 0.0f;

    g_issue(sb, Ah, Al, Bh, Bl, m0, n0, 0, K, N, tid);
    CP_COMMIT();
    g_issue(sb + STAGE_BYTES, Ah, Al, Bh, Bl, m0, n0, 1, K, N, tid);
    CP_COMMIT();

    for (int kt = 0; kt < NT; kt++) {
        CP_WAIT1();
        __syncthreads();
        const int pf = kt + 2;
        if (pf < NT)
            g_issue(sb + (pf % STAGES) * STAGE_BYTES, Ah, Al, Bh, Bl, m0, n0, pf, K, N, tid);
        CP_COMMIT();
        g_compute(sb + (kt % STAGES) * STAGE_BYTES, wid, lane, acc);
    }

    const int wm = (wid & 3) * 32, wn = (wid >> 2) * 32;
    const int g = lane >> 2, t = lane & 3;
#pragma unroll
    for (int mt = 0; mt < 2; mt++)
#pragma unroll
        for (int j = 0; j < 4; j++) {
            float* p = C + (size_t)(m0 + wm + mt * 16 + g) * N + n0 + wn + j * 8 + t * 2;
            float2 c0 = make_float2(acc[mt][j][0], acc[mt][j][1]);
            float2 c1 = make_float2(acc[mt][j][2], acc[mt][j][3]);
            *(float2*)p = c0;
            *(float2*)(p + (size_t)8 * N) = c1;
        }
}

// ---------------- hi/lo bf16 split (contiguous) ----------------
__global__ __launch_bounds__(256) void split_kernel(const float4* __restrict__ src,
                                                    uint2* __restrict__ h,
                                                    uint2* __restrict__ l, int n4) {
    int i = blockIdx.x * 256 + threadIdx.x;
    if (i >= n4) return;
    float4 v = src[i];
    uint32_t h01 = pkbf(v.x, v.y), h23 = pkbf(v.z, v.w);
    float hx = __uint_as_float(h01 << 16);
    float hy = __uint_as_float(h01 & 0xffff0000u);
    float hz = __uint_as_float(h23 << 16);
    float hw = __uint_as_float(h23 & 0xffff0000u);
    h[i] = make_uint2(h01, h23);
    l[i] = make_uint2(pkbf(v.x - hx, v.y - hy), pkbf(v.z - hz, v.w - hw));
}

// ---------------- hi/lo bf16 split into strided (concatenated) dest ----------------
__global__ __launch_bounds__(256) void splitWs_kernel(const float4* __restrict__ src,
                                                      __nv_bfloat16* __restrict__ dh,
                                                      __nv_bfloat16* __restrict__ dl,
                                                      int n4, int ncols4, int colOff) {
    int i = blockIdx.x * 256 + threadIdx.x;
    if (i >= n4) return;
    int row = i / ncols4;
    int c4 = i - row * ncols4;
    float4 v = src[i];
    uint32_t h01 = pkbf(v.x, v.y), h23 = pkbf(v.z, v.w);
    float hx = __uint_as_float(h01 << 16);
    float hy = __uint_as_float(h01 & 0xffff0000u);
    float hz = __uint_as_float(h23 << 16);
    float hw = __uint_as_float(h23 & 0xffff0000u);
    size_t o = (size_t)row * PST + colOff + c4 * 4;
    *(uint2*)(dh + o) = make_uint2(h01, h23);
    *(uint2*)(dl + o) = make_uint2(pkbf(v.x - hx, v.y - hy), pkbf(v.z - hz, v.w - hw));
}

// ---------------- gate projections: g -> exp(g), beta ----------------
__global__ __launch_bounds__(256) void gate_kernel(const float* __restrict__ H,
                                                   const float* __restrict__ Wa,
                                                   const float* __restrict__ Wb,
                                                   const float* __restrict__ A_log,
                                                   const float* __restrict__ dt_bias) {
    __shared__ float hrow[HID];
    const int bt = blockIdx.x;
    const int tid = threadIdx.x;
    for (int i = tid; i < HID; i += 256) hrow[i] = H[(size_t)bt * HID + i];
    __syncthreads();
    const int w = tid >> 5, lane = tid & 31;
    for (int d = w; d < 12; d += 8) {
        const int head = d % 6;
        const float* Wc = (d < 6) ? Wa : Wb;
        float s = 0.0f;
        for (int i = lane; i < HID; i += 32) s += hrow[i] * Wc[i * NH + head];
#pragma unroll
        for (int m = 16; m > 0; m >>= 1) s += __shfl_xor_sync(0xffffffffu, s, m);
        if (lane == 0) {
            if (d < 6) {
                float x = s + dt_bias[head];
                float sp = (x > 20.0f) ? x : log1pf(expf(x));
                float g = -expf(A_log[head]) * sp;
                d_EG[bt * NH + head] = expf(g);
            } else {
                d_Beta[bt * NH + head] = sigm(s);
            }
        }
    }
}

// ---------------- causal depthwise conv + silu + per-head l2norm (q/k) ----------------
__global__ __launch_bounds__(256) void convqk_kernel(const float* __restrict__ P,
                                                     const float* __restrict__ W,
                                                     float* __restrict__ out,
                                                     float scale, int colOff) {
    const int bt = blockIdx.x;
    const int h = blockIdx.y;
    const int c = threadIdx.x;
    const int ch = h * DK + c;
    const int t = bt & (T_ - 1);
    float acc = 0.0f;
#pragma unroll
    for (int j = 0; j < CK; j++) {
        int tt = t - (CK - 1) + j;
        if (tt >= 0) acc += P[(size_t)(bt - (CK - 1) + j) * PST + colOff + ch] * W[ch * CK + j];
    }
    float y = acc * sigm(acc);  // silu

    __shared__ float red[8];
    float ss = y * y;
#pragma unroll
    for (int m = 16; m > 0; m >>= 1) ss += __shfl_xor_sync(0xffffffffu, ss, m);
    if ((c & 31) == 0) red[c >> 5] = ss;
    __syncthreads();
    float tot = 0.0f;
#pragma unroll
    for (int i = 0; i < 8; i++) tot += red[i];
    float r = rsqrtf(tot + 1e-6f);
    out[(size_t)bt * KD + ch] = y * r * scale;
}

// ---------------- causal depthwise conv + silu (v) ----------------
__global__ __launch_bounds__(256) void convv_kernel(const float* __restrict__ P,
                                                    const float* __restrict__ W) {
    const int bt = blockIdx.x;
    const int ch = blockIdx.y * 256 + threadIdx.x;
    const int t = bt & (T_ - 1);
    float acc = 0.0f;
#pragma unroll
    for (int j = 0; j < CK; j++) {
        int tt = t - (CK - 1) + j;
        if (tt >= 0) acc += P[(size_t)(bt - (CK - 1) + j) * PST + VOFF + ch] * W[ch * CK + j];
    }
    d_Vc[(size_t)bt * VD + ch] = acc * sigm(acc);
}

// ---------------- gated delta-rule recurrence (cp.async smem ring, 12 slots) ----------------
// 96 CTAs: (b,h) x 8 chunks of 64 cols. warp owns 8 cols; lane=(rg,cg):
// rg 0..15 -> 16 rows; cg 0..1 -> 4 cols. Ring: 12 slots of {k256,q256,v64,eg,beta};
// prefetch distance 6, ONE barrier per 4 timesteps. Per iteration: reads slots
// t..t+3 (mod 12), writes slots t+6..t+9 (mod 12) -- disjoint; wait_group 2
// leaves groups t+4,t+5 outstanding so data t..t+3 are complete.
#define RSLOT 640   // floats per slot (2560B)
__global__ __launch_bounds__(256, 1) void recur_kernel() {
    __shared__ __align__(16) float ring[12][RSLOT];
    const int bid = blockIdx.x;
    const int chunk = bid & 7;
    const int bh = bid >> 3;
    const int b = bh / NH, h = bh % NH;
    const int tid = threadIdx.x;
    const int warp = tid >> 5, lane = tid & 31;
    const int rg = lane >> 1, cg = lane & 1;
    const int bt0 = b * T_;

    const float* Kb = d_Kc + h * DK;
    const float* Qb = d_Qc + h * DK;
    const float* Vb = d_Vc + h * DV + chunk * 64;
    float* Ob = d_O + h * DV + chunk * 64 + warp * 8 + cg * 4;

    ull S[16][2];
#pragma unroll
    for (int r = 0; r < 16; r++) { S[r][0] = 0ull; S[r][1] = 0ull; }

    // producer: each thread issues <=1 cp.async per timestep
    auto issue = [&](int slot, int t) {
        const int bt = bt0 + t;
        uint32_t sd = smem_u32(&ring[slot][0]);
        if (tid < 64) {
            cpa16(sd + tid * 16, Kb + (size_t)bt * KD + tid * 4);
        } else if (tid < 128) {
            cpa16(sd + 1024 + (tid - 64) * 16, Qb + (size_t)bt * KD + (tid - 64) * 4);
        } else if (tid < 144) {
            cpa16(sd + 2048 + (tid - 128) * 16, Vb + (size_t)bt * VD + (tid - 128) * 4);
        } else if (tid == 144) {
            cpa4(sd + 2304, d_EG + bt * NH + h);
        } else if (tid == 145) {
            cpa4(sd + 2308, d_Beta + bt * NH + h);
        }
    };

    // consumer body for one timestep (data must be visible in its ring slot)
    auto step = [&](int t, int slot) {
        const float* sl = ring[slot];
        float kf[16], qf[16];
#pragma unroll
        for (int j = 0; j < 4; j++) {
            float4 a = *(const float4*)(sl + rg * 16 + j * 4);
            kf[4 * j] = a.x; kf[4 * j + 1] = a.y; kf[4 * j + 2] = a.z; kf[4 * j + 3] = a.w;
            float4 qd = *(const float4*)(sl + 256 + rg * 16 + j * 4);
            qf[4 * j] = qd.x; qf[4 * j + 1] = qd.y; qf[4 * j + 2] = qd.z; qf[4 * j + 3] = qd.w;
        }
        float4 vv = *(const float4*)(sl + 512 + warp * 8 + cg * 4);
        const float eg = sl[576];
        const float bet = sl[577];

        // phase 1: kv = k . S (pre-decay)
        ull kv2a = 0ull, kv2b = 0ull;
#pragma unroll
        for (int r = 0; r < 16; r++) {
            ull k2 = pack2(kf[r], kf[r]);
            kv2a = fma2(k2, S[r][0], kv2a);
            kv2b = fma2(k2, S[r][1], kv2b);
        }
#pragma unroll
        for (int mask = 2; mask <= 16; mask <<= 1) {
            kv2a = add2(kv2a, __shfl_xor_sync(0xffffffffu, kv2a, mask));
            kv2b = add2(kv2b, __shfl_xor_sync(0xffffffffu, kv2b, mask));
        }
        float kv0, kv1, kv2f, kv3;
        unpack2(kv2a, kv0, kv1);
        unpack2(kv2b, kv2f, kv3);

        ull u2a = pack2((vv.x - eg * kv0) * bet, (vv.y - eg * kv1) * bet);
        ull u2b = pack2((vv.z - eg * kv2f) * bet, (vv.w - eg * kv3) * bet);
        const ull eg2 = pack2(eg, eg);

        // phase 2: S = eg*S + k (x) u ; o = q . S
        ull o2a = 0ull, o2b = 0ull;
#pragma unroll
        for (int r = 0; r < 16; r++) {
            ull k2 = pack2(kf[r], kf[r]);
            ull q2 = pack2(qf[r], qf[r]);
            S[r][0] = fma2(eg2, S[r][0], mul2(k2, u2a));
            o2a = fma2(q2, S[r][0], o2a);
            S[r][1] = fma2(eg2, S[r][1], mul2(k2, u2b));
            o2b = fma2(q2, S[r][1], o2b);
        }
#pragma unroll
        for (int mask = 2; mask <= 16; mask <<= 1) {
            o2a = add2(o2a, __shfl_xor_sync(0xffffffffu, o2a, mask));
            o2b = add2(o2b, __shfl_xor_sync(0xffffffffu, o2b, mask));
        }
        if (rg == 0) {
            float4 o4;
            unpack2(o2a, o4.x, o4.y);
            unpack2(o2b, o4.z, o4.w);
            *(float4*)(Ob + (size_t)(bt0 + t) * VD) = o4;
        }
    };

    // prime groups carrying data 0..5 (one commit each)
#pragma unroll
    for (int p = 0; p < 6; p++) { issue(p, p); CP_COMMIT(); }

    int slot = 0;   // slot of data t (t mod 12, tracked incrementally)
    int wsl = 6;    // slot of next write (data t+6 mod 12)
    for (int t = 0; t < T_; t += 4) {
        CP_WAIT2();           // data t..t+3 complete (2 newest groups may be in flight)
        __syncthreads();      // all warps done reading the slots we are about to write

#pragma unroll
        for (int u = 0; u < 4; u++) {
            if (t + 6 + u < T_) issue(wsl, t + 6 + u);
            CP_COMMIT();
            step(t + u, slot);
            slot = (slot + 1 == 12) ? 0 : slot + 1;
            wsl = (wsl + 1 == 12) ? 0 : wsl + 1;
        }
    }
}

// ---------------- gated RMSNorm + bf16 hi/lo split (fused) ----------------
__global__ __launch_bounds__(256) void normgate_kernel(const float* __restrict__ w) {
    const int bt = blockIdx.x;
    const int h = blockIdx.y;
    const int tid = threadIdx.x;
    const size_t obase = (size_t)bt * VD + h * DV;
    const size_t gbase = (size_t)bt * PST + GOFF + h * DV;
    float o0 = d_O[obase + tid];
    float o1 = d_O[obase + tid + 256];
    float ss = o0 * o0 + o1 * o1;
    __shared__ float red[8];
#pragma unroll
    for (int m = 16; m > 0; m >>= 1) ss += __shfl_xor_sync(0xffffffffu, ss, m);
    if ((tid & 31) == 0) red[tid >> 5] = ss;
    __syncthreads();
    float tot = 0.0f;
#pragma unroll
    for (int i = 0; i < 8; i++) tot += red[i];
    float rms = rsqrtf(tot * (1.0f / (float)DV) + 1e-5f);
    float g0 = d_P[gbase + tid];
    float g1 = d_P[gbase + tid + 256];
    float r0 = o0 * rms * w[tid]       * g0 * sigm(g0);
    float r1 = o1 * rms * w[tid + 256] * g1 * sigm(g1);
    // fused bf16 hi/lo split
    uint32_t hp = pkbf(r0, r1);
    float h0 = __uint_as_float(hp << 16);
    float h1 = __uint_as_float(hp & 0xffff0000u);
    uint32_t lp = pkbf(r0 - h0, r1 - h1);
    d_Gh[obase + tid]       = __ushort_as_bfloat16((unsigned short)(hp & 0xffff));
    d_Gh[obase + tid + 256] = __ushort_as_bfloat16((unsigned short)(hp >> 16));
    d_Gl[obase + tid]       = __ushort_as_bfloat16((unsigned short)(lp & 0xffff));
    d_Gl[obase + tid + 256] = __ushort_as_bfloat16((unsigned short)(lp >> 16));
}

// ---------------- streams/events (created once at static init) ----------------
struct GdnStreams {
    cudaStream_t s1, s2;
    cudaEvent_t evRoot, evW1, evW2, evWo, evGB, evP, evK, evV;
    GdnStreams() {
        cudaStreamCreateWithFlags(&s1, cudaStreamNonBlocking);
        cudaStreamCreateWithFlags(&s2, cudaStreamNonBlocking);
        cudaEventCreateWithFlags(&evRoot, cudaEventDisableTiming);
        cudaEventCreateWithFlags(&evW1, cudaEventDisableTiming);
        cudaEventCreateWithFlags(&evW2, cudaEventDisableTiming);
        cudaEventCreateWithFlags(&evWo, cudaEventDisableTiming);
        cudaEventCreateWithFlags(&evGB, cudaEventDisableTiming);
        cudaEventCreateWithFlags(&evP, cudaEventDisableTiming);
        cudaEventCreateWithFlags(&evK, cudaEventDisableTiming);
        cudaEventCreateWithFlags(&evV, cudaEventDisableTiming);
    }
};
static GdnStreams g_s;

// ---------------- host launcher ----------------
extern "C" void kernel_launch(void* const* d_in, const int* in_sizes, int n_in,
                              void* d_out, int out_size) {
    const float* H       = (const float*)d_in[0];
    const float* Wq      = (const float*)d_in[1];
    const float* Wk      = (const float*)d_in[2];
    const float* Wv      = (const float*)d_in[3];
    const float* Wa      = (const float*)d_in[4];
    const float* Wb      = (const float*)d_in[5];
    const float* Wg      = (const float*)d_in[6];
    const float* Wo      = (const float*)d_in[7];
    const float* conv_q  = (const float*)d_in[8];
    const float* conv_k  = (const float*)d_in[9];
    const float* conv_v  = (const float*)d_in[10];
    const float* A_log   = (const float*)d_in[11];
    const float* dt_bias = (const float*)d_in[12];
    const float* onw     = (const float*)d_in[13];

    float *pp, *qc, *kc;
    cudaGetSymbolAddress((void**)&pp, d_P);
    cudaGetSymbolAddress((void**)&qc, d_Qc);
    cudaGetSymbolAddress((void**)&kc, d_Kc);

    __nv_bfloat16 *hh, *hl, *wbh, *wbl, *woh, *wol, *gh, *gl;
    cudaGetSymbolAddress((void**)&hh, d_Hh);   cudaGetSymbolAddress((void**)&hl, d_Hl);
    cudaGetSymbolAddress((void**)&wbh, d_Wbh); cudaGetSymbolAddress((void**)&wbl, d_Wbl);
    cudaGetSymbolAddress((void**)&woh, d_Woh); cudaGetSymbolAddress((void**)&wol, d_Wol);
    cudaGetSymbolAddress((void**)&gh, d_Gh);   cudaGetSymbolAddress((void**)&gl, d_Gl);

    cudaFuncSetAttribute(gemm_bf, cudaFuncAttributeMaxDynamicSharedMemorySize, SMEM_GB);

    cudaStream_t s0 = 0;
    cudaStream_t s1 = g_s.s1, s2 = g_s.s2;

    // ---- fork: root event on origin stream so side streams join the capture ----
    cudaEventRecord(g_s.evRoot, s0);
    cudaStreamWaitEvent(s1, g_s.evRoot, 0);
    cudaStreamWaitEvent(s2, g_s.evRoot, 0);

    // s0: split H
    {
        int n4 = (BT * HID) / 4;
        split_kernel<<<(n4 + 255) / 256, 256, 0, s0>>>((const float4*)H, (uint2*)hh, (uint2*)hl, n4);
    }
    // s1: Wq/Wk/Wv splits into concatenated buffer
    {
        int n4q = (HID * KD) / 4;
        splitWs_kernel<<<(n4q + 255) / 256, 256, 0, s1>>>((const float4*)Wq, wbh, wbl, n4q, KD / 4, QOFF);
        splitWs_kernel<<<(n4q + 255) / 256, 256, 0, s1>>>((const float4*)Wk, wbh, wbl, n4q, KD / 4, KOFF);
        int n4v = (HID * VD) / 4;
        splitWs_kernel<<<(n4v + 255) / 256, 256, 0, s1>>>((const float4*)Wv, wbh, wbl, n4v, VD / 4, VOFF);
        cudaEventRecord(g_s.evW1, s1);
    }
    // s2: Wg split + Wo split + gate projections
    {
        int n4v = (HID * VD) / 4;
        splitWs_kernel<<<(n4v + 255) / 256, 256, 0, s2>>>((const float4*)Wg, wbh, wbl, n4v, VD / 4, GOFF);
        cudaEventRecord(g_s.evW2, s2);
        int n4o = (VD * HID) / 4;
        split_kernel<<<(n4o + 255) / 256, 256, 0, s2>>>((const float4*)Wo, (uint2*)woh, (uint2*)wol, n4o);
        cudaEventRecord(g_s.evWo, s2);
        gate_kernel<<<BT, 256, 0, s2>>>(H, Wa, Wb, A_log, dt_bias);
        cudaEventRecord(g_s.evGB, s2);
    }

    // ---- ONE fused projection GEMM: [4096 x 9216] ----
    cudaStreamWaitEvent(s0, g_s.evW1, 0);
    cudaStreamWaitEvent(s0, g_s.evW2, 0);
    gemm_bf<<<dim3(PST / BN, BT / BM), 256, SMEM_GB, s0>>>(hh, hl, wbh, wbl, pp, BT, PST, HID);
    cudaEventRecord(g_s.evP, s0);

    // ---- convs (3-way concurrent) ----
    convqk_kernel<<<dim3(BT, NH), 256, 0, s0>>>(pp, conv_q, qc, 0.0625f, QOFF);
    cudaStreamWaitEvent(s1, g_s.evP, 0);
    convqk_kernel<<<dim3(BT, NH), 256, 0, s1>>>(pp, conv_k, kc, 1.0f, KOFF);
    cudaEventRecord(g_s.evK, s1);
    cudaStreamWaitEvent(s2, g_s.evP, 0);
    convv_kernel<<<dim3(BT, VD / 256), 256, 0, s2>>>(pp, conv_v);
    cudaEventRecord(g_s.evV, s2);

    // ---- recurrence ----
    cudaStreamWaitEvent(s0, g_s.evK, 0);
    cudaStreamWaitEvent(s0, g_s.evV, 0);
    cudaStreamWaitEvent(s0, g_s.evGB, 0);
    recur_kernel<<<96, 256, 0, s0>>>();

    // ---- epilogue: fused normgate+split, then Wo GEMM ----
    normgate_kernel<<<dim3(BT, NH), 256, 0, s0>>>(onw);
    cudaStreamWaitEvent(s0, g_s.evWo, 0);
    gemm_bf<<<dim3(HID / BN, BT / BM), 256, SMEM_GB, s0>>>(gh, gl, woh, wol, (float*)d_out, BT, HID, VD);
}

// round 17
// speedup vs baseline: 1.0104x; 1.0104x over previous
#include <cuda_runtime.h>
#include <cuda_bf16.h>
#include <cstdint>

// ---------------- problem dims ----------------
#define B_   2
#define T_   2048
#define HID  2048
#define NH   6
#define DK   256
#define DV   512
#define KD   1536      // NH*DK
#define VD   3072      // NH*DV
#define BT   4096      // B_*T_
#define CK   4

// fused projection layout: [q(1536) | k(1536) | v(3072) | g(3072)]
#define PST  9216
#define QOFF 0
#define KOFF 1536
#define VOFF 3072
#define GOFF 6144

typedef unsigned long long ull;

// ---------------- scratch (device globals; no allocs allowed) ----------------
__device__ float d_P[(size_t)BT * PST];       // fused projection output (fp32)
__device__ float d_Qc[BT * KD];
__device__ float d_Kc[BT * KD];
__device__ float d_Vc[(size_t)BT * VD];
__device__ float d_EG[BT * NH];
__device__ float d_Beta[BT * NH];
__device__ float d_O[(size_t)BT * VD];

// bf16 split operand buffers
__device__ __nv_bfloat16 d_Hh[(size_t)BT * HID];
__device__ __nv_bfloat16 d_Hl[(size_t)BT * HID];
__device__ __nv_bfloat16 d_Wbh[(size_t)HID * PST];   // [Wq|Wk|Wv|Wg] hi
__device__ __nv_bfloat16 d_Wbl[(size_t)HID * PST];   // lo
__device__ __nv_bfloat16 d_Woh[(size_t)VD * HID];
__device__ __nv_bfloat16 d_Wol[(size_t)VD * HID];
__device__ __nv_bfloat16 d_Gh[(size_t)BT * VD];
__device__ __nv_bfloat16 d_Gl[(size_t)BT * VD];

// ---------------- packed f32x2 helpers (recurrence) ----------------
__device__ __forceinline__ ull fma2(ull a, ull b, ull c) {
    ull d;
    asm("fma.rn.f32x2 %0, %1, %2, %3;" : "=l"(d) : "l"(a), "l"(b), "l"(c));
    return d;
}
__device__ __forceinline__ ull mul2(ull a, ull b) {
    ull d;
    asm("mul.rn.f32x2 %0, %1, %2;" : "=l"(d) : "l"(a), "l"(b));
    return d;
}
__device__ __forceinline__ ull add2(ull a, ull b) {
    ull d;
    asm("add.rn.f32x2 %0, %1, %2;" : "=l"(d) : "l"(a), "l"(b));
    return d;
}
__device__ __forceinline__ ull pack2(float lo, float hi) {
    ull d;
    asm("mov.b64 %0, {%1, %2};" : "=l"(d) : "f"(lo), "f"(hi));
    return d;
}
__device__ __forceinline__ void unpack2(ull v, float& lo, float& hi) {
    asm("mov.b64 {%0, %1}, %2;" : "=f"(lo), "=f"(hi) : "l"(v));
}
__device__ __forceinline__ float sigm(float x) { return 1.0f / (1.0f + __expf(-x)); }

// ---------------- mma.sync bf16 GEMM machinery ----------------
__device__ __forceinline__ uint32_t smem_u32(const void* p) {
    uint32_t a;
    asm("{ .reg .u64 t; cvta.to.shared.u64 t, %1; cvt.u32.u64 %0, t; }" : "=r"(a) : "l"(p));
    return a;
}
__device__ __forceinline__ uint32_t pkbf(float x, float y) {
    uint32_t r;
    asm("cvt.rn.bf16x2.f32 %0, %1, %2;" : "=r"(r) : "f"(y), "f"(x));
    return r;
}
__device__ __forceinline__ void ldsm_x4(uint32_t* r, uint32_t a) {
    asm volatile("ldmatrix.sync.aligned.m8n8.x4.shared.b16 {%0,%1,%2,%3}, [%4];"
                 : "=r"(r[0]), "=r"(r[1]), "=r"(r[2]), "=r"(r[3]) : "r"(a));
}
__device__ __forceinline__ void ldsm_x4_t(uint32_t* r, uint32_t a) {
    asm volatile("ldmatrix.sync.aligned.m8n8.x4.trans.shared.b16 {%0,%1,%2,%3}, [%4];"
                 : "=r"(r[0]), "=r"(r[1]), "=r"(r[2]), "=r"(r[3]) : "r"(a));
}
__device__ __forceinline__ void mma_bf16(float* d, const uint32_t* a, const uint32_t* b) {
    asm volatile(
        "mma.sync.aligned.m16n8k16.row.col.f32.bf16.bf16.f32 "
        "{%0,%1,%2,%3}, {%4,%5,%6,%7}, {%8,%9}, {%0,%1,%2,%3};"
        : "+f"(d[0]), "+f"(d[1]), "+f"(d[2]), "+f"(d[3])
        : "r"(a[0]), "r"(a[1]), "r"(a[2]), "r"(a[3]), "r"(b[0]), "r"(b[1]));
}
__device__ __forceinline__ void cpa16(uint32_t dst, const void* src) {
    asm volatile("cp.async.cg.shared.global [%0], [%1], 16;" :: "r"(dst), "l"(src));
}
__device__ __forceinline__ void cpa4(uint32_t dst, const void* src) {
    asm volatile("cp.async.ca.shared.global [%0], [%1], 4;" :: "r"(dst), "l"(src));
}
#define CP_COMMIT() asm volatile("cp.async.commit_group;" ::: "memory")
#define CP_WAIT1()  asm volatile("cp.async.wait_group 1;" ::: "memory")
#define CP_WAIT3()  asm volatile("cp.async.wait_group 3;" ::: "memory")

// tiles: 128(M) x 64(N), BK=32, 3 stages, 2 CTAs/SM
#define BM 128
#define BN 64
#define BKf 32
#define STAGES 3
#define A_STR 80
#define B_STR 144
#define AT_BYTES (128 * A_STR)
#define BTI_BYTES (32 * B_STR)
#define OFF_AH 0
#define OFF_AL AT_BYTES
#define OFF_BH (2 * AT_BYTES)
#define OFF_BL (2 * AT_BYTES + BTI_BYTES)
#define STAGE_BYTES (2 * AT_BYTES + 2 * BTI_BYTES)
#define SMEM_GB (STAGES * STAGE_BYTES)

__device__ __forceinline__ void g_issue(uint32_t st,
                                        const __nv_bfloat16* __restrict__ Ah,
                                        const __nv_bfloat16* __restrict__ Al,
                                        const __nv_bfloat16* __restrict__ Bh,
                                        const __nv_bfloat16* __restrict__ Bl,
                                        int m0, int n0, int kt, int K, int N, int tid) {
#pragma unroll
    for (int half = 0; half < 2; half++) {
        int r = (tid >> 2) + half * 64;
        int ke = (tid & 3) * 8;
        const size_t ga = (size_t)(m0 + r) * K + kt * BKf + ke;
        uint32_t so = st + r * A_STR + ke * 2;
        cpa16(so + OFF_AH, Ah + ga);
        cpa16(so + OFF_AL, Al + ga);
    }
    {
        int r = tid >> 3;
        int ke = (tid & 7) * 8;
        const size_t gb = (size_t)(kt * BKf + r) * N + n0 + ke;
        uint32_t so = st + r * B_STR + ke * 2;
        cpa16(so + OFF_BH, Bh + gb);
        cpa16(so + OFF_BL, Bl + gb);
    }
}

__device__ __forceinline__ void g_compute(uint32_t st, int wid, int lane, float (*acc)[4][4]) {
    const int wm = (wid & 3) * 32, wn = (wid >> 2) * 32;
    const int arow = lane & 15;
    const int acg = (lane >> 4) * 8;
    const int brow = (lane & 7) + ((lane >> 3) & 1) * 8;
    const int bcg = (lane >> 4) * 8;
#pragma unroll
    for (int ks = 0; ks < BKf; ks += 16) {
        uint32_t ah[2][4], al[2][4], bh[2][4], bl[2][4];
#pragma unroll
        for (int mt = 0; mt < 2; mt++) {
            uint32_t ad = st + OFF_AH + (wm + mt * 16 + arow) * A_STR + (ks + acg) * 2;
            ldsm_x4(ah[mt], ad);
            ldsm_x4(al[mt], ad + (OFF_AL - OFF_AH));
        }
#pragma unroll
        for (int nt = 0; nt < 2; nt++) {
            uint32_t bd = st + OFF_BH + (ks + brow) * B_STR + (wn + nt * 16 + bcg) * 2;
            ldsm_x4_t(bh[nt], bd);
            ldsm_x4_t(bl[nt], bd + (OFF_BL - OFF_BH));
        }
#pragma unroll
        for (int mt = 0; mt < 2; mt++)
#pragma unroll
            for (int j = 0; j < 4; j++)
                mma_bf16(acc[mt][j], ah[mt], &bh[j >> 1][(j & 1) * 2]);
#pragma unroll
        for (int mt = 0; mt < 2; mt++)
#pragma unroll
            for (int j = 0; j < 4; j++)
                mma_bf16(acc[mt][j], ah[mt], &bl[j >> 1][(j & 1) * 2]);
#pragma unroll
        for (int mt = 0; mt < 2; mt++)
#pragma unroll
            for (int j = 0; j < 4; j++)
                mma_bf16(acc[mt][j], al[mt], &bh[j >> 1][(j & 1) * 2]);
    }
}

// C[M,N] = A[M,K] @ B[K,N]; operands pre-split hi/lo bf16, fp32 out
__global__ __launch_bounds__(256, 2) void gemm_bf(const __nv_bfloat16* __restrict__ Ah,
                                                  const __nv_bfloat16* __restrict__ Al,
                                                  const __nv_bfloat16* __restrict__ Bh,
                                                  const __nv_bfloat16* __restrict__ Bl,
                                                  float* __restrict__ C,
                                                  int M, int N, int K) {
    extern __shared__ char smem[];
    const uint32_t sb = smem_u32(smem);
    const int tid = threadIdx.x, lane = tid & 31, wid = tid >> 5;
    const int m0 = blockIdx.y * BM, n0 = blockIdx.x * BN;
    const int NT = K / BKf;

    float acc[2][4][4];
#pragma unroll
    for (int mt = 0; mt < 2; mt++)
#pragma unroll
        for (int j = 0; j < 4; j++)
#pragma unroll
            for (int p = 0; p < 4; p++) acc[mt][j][p] = 0.0f;

    g_issue(sb, Ah, Al, Bh, Bl, m0, n0, 0, K, N, tid);
    CP_COMMIT();
    g_issue(sb + STAGE_BYTES, Ah, Al, Bh, Bl, m0, n0, 1, K, N, tid);
    CP_COMMIT();

    for (int kt = 0; kt < NT; kt++) {
        CP_WAIT1();
        __syncthreads();
        const int pf = kt + 2;
        if (pf < NT)
            g_issue(sb + (pf % STAGES) * STAGE_BYTES, Ah, Al, Bh, Bl, m0, n0, pf, K, N, tid);
        CP_COMMIT();
        g_compute(sb + (kt % STAGES) * STAGE_BYTES, wid, lane, acc);
    }

    const int wm = (wid & 3) * 32, wn = (wid >> 2) * 32;
    const int g = lane >> 2, t = lane & 3;
#pragma unroll
    for (int mt = 0; mt < 2; mt++)
#pragma unroll
        for (int j = 0; j < 4; j++) {
            float* p = C + (size_t)(m0 + wm + mt * 16 + g) * N + n0 + wn + j * 8 + t * 2;
            float2 c0 = make_float2(acc[mt][j][0], acc[mt][j][1]);
            float2 c1 = make_float2(acc[mt][j][2], acc[mt][j][3]);
            *(float2*)p = c0;
            *(float2*)(p + (size_t)8 * N) = c1;
        }
}

// ---------------- hi/lo bf16 split (contiguous) ----------------
__global__ __launch_bounds__(256) void split_kernel(const float4* __restrict__ src,
                                                    uint2* __restrict__ h,
                                                    uint2* __restrict__ l, int n4) {
    int i = blockIdx.x * 256 + threadIdx.x;
    if (i >= n4) return;
    float4 v = src[i];
    uint32_t h01 = pkbf(v.x, v.y), h23 = pkbf(v.z, v.w);
    float hx = __uint_as_float(h01 << 16);
    float hy = __uint_as_float(h01 & 0xffff0000u);
    float hz = __uint_as_float(h23 << 16);
    float hw = __uint_as_float(h23 & 0xffff0000u);
    h[i] = make_uint2(h01, h23);
    l[i] = make_uint2(pkbf(v.x - hx, v.y - hy), pkbf(v.z - hz, v.w - hw));
}

// ---------------- hi/lo bf16 split into strided (concatenated) dest ----------------
__global__ __launch_bounds__(256) void splitWs_kernel(const float4* __restrict__ src,
                                                      __nv_bfloat16* __restrict__ dh,
                                                      __nv_bfloat16* __restrict__ dl,
                                                      int n4, int ncols4, int colOff) {
    int i = blockIdx.x * 256 + threadIdx.x;
    if (i >= n4) return;
    int row = i / ncols4;
    int c4 = i - row * ncols4;
    float4 v = src[i];
    uint32_t h01 = pkbf(v.x, v.y), h23 = pkbf(v.z, v.w);
    float hx = __uint_as_float(h01 << 16);
    float hy = __uint_as_float(h01 & 0xffff0000u);
    float hz = __uint_as_float(h23 << 16);
    float hw = __uint_as_float(h23 & 0xffff0000u);
    size_t o = (size_t)row * PST + colOff + c4 * 4;
    *(uint2*)(dh + o) = make_uint2(h01, h23);
    *(uint2*)(dl + o) = make_uint2(pkbf(v.x - hx, v.y - hy), pkbf(v.z - hz, v.w - hw));
}

// ---------------- gate projections: g -> exp(g), beta ----------------
__global__ __launch_bounds__(256) void gate_kernel(const float* __restrict__ H,
                                                   const float* __restrict__ Wa,
                                                   const float* __restrict__ Wb,
                                                   const float* __restrict__ A_log,
                                                   const float* __restrict__ dt_bias) {
    __shared__ float hrow[HID];
    const int bt = blockIdx.x;
    const int tid = threadIdx.x;
    for (int i = tid; i < HID; i += 256) hrow[i] = H[(size_t)bt * HID + i];
    __syncthreads();
    const int w = tid >> 5, lane = tid & 31;
    for (int d = w; d < 12; d += 8) {
        const int head = d % 6;
        const float* Wc = (d < 6) ? Wa : Wb;
        float s = 0.0f;
        for (int i = lane; i < HID; i += 32) s += hrow[i] * Wc[i * NH + head];
#pragma unroll
        for (int m = 16; m > 0; m >>= 1) s += __shfl_xor_sync(0xffffffffu, s, m);
        if (lane == 0) {
            if (d < 6) {
                float x = s + dt_bias[head];
                float sp = (x > 20.0f) ? x : log1pf(expf(x));
                float g = -expf(A_log[head]) * sp;
                d_EG[bt * NH + head] = expf(g);
            } else {
                d_Beta[bt * NH + head] = sigm(s);
            }
        }
    }
}

// ---------------- causal depthwise conv + silu + per-head l2norm (q/k) ----------------
__global__ __launch_bounds__(256) void convqk_kernel(const float* __restrict__ P,
                                                     const float* __restrict__ W,
                                                     float* __restrict__ out,
                                                     float scale, int colOff) {
    const int bt = blockIdx.x;
    const int h = blockIdx.y;
    const int c = threadIdx.x;
    const int ch = h * DK + c;
    const int t = bt & (T_ - 1);
    float acc = 0.0f;
#pragma unroll
    for (int j = 0; j < CK; j++) {
        int tt = t - (CK - 1) + j;
        if (tt >= 0) acc += P[(size_t)(bt - (CK - 1) + j) * PST + colOff + ch] * W[ch * CK + j];
    }
    float y = acc * sigm(acc);  // silu

    __shared__ float red[8];
    float ss = y * y;
#pragma unroll
    for (int m = 16; m > 0; m >>= 1) ss += __shfl_xor_sync(0xffffffffu, ss, m);
    if ((c & 31) == 0) red[c >> 5] = ss;
    __syncthreads();
    float tot = 0.0f;
#pragma unroll
    for (int i = 0; i < 8; i++) tot += red[i];
    float r = rsqrtf(tot + 1e-6f);
    out[(size_t)bt * KD + ch] = y * r * scale;
}

// ---------------- causal depthwise conv + silu (v) ----------------
__global__ __launch_bounds__(256) void convv_kernel(const float* __restrict__ P,
                                                    const float* __restrict__ W) {
    const int bt = blockIdx.x;
    const int ch = blockIdx.y * 256 + threadIdx.x;
    const int t = bt & (T_ - 1);
    float acc = 0.0f;
#pragma unroll
    for (int j = 0; j < CK; j++) {
        int tt = t - (CK - 1) + j;
        if (tt >= 0) acc += P[(size_t)(bt - (CK - 1) + j) * PST + VOFF + ch] * W[ch * CK + j];
    }
    d_Vc[(size_t)bt * VD + ch] = acc * sigm(acc);
}

// ---------------- gated delta-rule recurrence (cp.async ring, factored decay) ----------------
// 96 CTAs: (b,h) x 8 chunks of 64 cols. warp owns 8 cols; lane=(rg,cg):
// rg 0..15 -> 16 rows; cg 0..1 -> 4 cols. Ring: 8 slots of {k256,q256,v64,eg,beta};
// prefetch distance 5, ONE barrier per 2 timesteps (R14 scheme).
// State kept SCALED: Shat = S / D, D = running prod of eg (rescale when D < 1e-18).
// Update becomes pure fma (no per-element decay multiply): Shat += k (x) (u/Dn).
#define RSLOT 640   // floats per slot (2560B)
__global__ __launch_bounds__(256, 1) void recur_kernel() {
    __shared__ __align__(16) float ring[8][RSLOT];
    const int bid = blockIdx.x;
    const int chunk = bid & 7;
    const int bh = bid >> 3;
    const int b = bh / NH, h = bh % NH;
    const int tid = threadIdx.x;
    const int warp = tid >> 5, lane = tid & 31;
    const int rg = lane >> 1, cg = lane & 1;
    const int bt0 = b * T_;

    const float* Kb = d_Kc + h * DK;
    const float* Qb = d_Qc + h * DK;
    const float* Vb = d_Vc + h * DV + chunk * 64;
    float* Ob = d_O + h * DV + chunk * 64 + warp * 8 + cg * 4;

    ull S[16][2];
#pragma unroll
    for (int r = 0; r < 16; r++) { S[r][0] = 0ull; S[r][1] = 0ull; }
    float Dcur = 1.0f;

    // producer: each thread issues <=1 cp.async per timestep
    auto issue = [&](int slot, int t) {
        const int bt = bt0 + t;
        uint32_t sd = smem_u32(&ring[slot][0]);
        if (tid < 64) {
            cpa16(sd + tid * 16, Kb + (size_t)bt * KD + tid * 4);
        } else if (tid < 128) {
            cpa16(sd + 1024 + (tid - 64) * 16, Qb + (size_t)bt * KD + (tid - 64) * 4);
        } else if (tid < 144) {
            cpa16(sd + 2048 + (tid - 128) * 16, Vb + (size_t)bt * VD + (tid - 128) * 4);
        } else if (tid == 144) {
            cpa4(sd + 2304, d_EG + bt * NH + h);
        } else if (tid == 145) {
            cpa4(sd + 2308, d_Beta + bt * NH + h);
        }
    };

    // consumer body for one timestep (data must be visible in ring[t&7])
    auto step = [&](int t) {
        const float* sl = ring[t & 7];
        float kf[16], qf[16];
#pragma unroll
        for (int j = 0; j < 4; j++) {
            float4 a = *(const float4*)(sl + rg * 16 + j * 4);
            kf[4 * j] = a.x; kf[4 * j + 1] = a.y; kf[4 * j + 2] = a.z; kf[4 * j + 3] = a.w;
            float4 qd = *(const float4*)(sl + 256 + rg * 16 + j * 4);
            qf[4 * j] = qd.x; qf[4 * j + 1] = qd.y; qf[4 * j + 2] = qd.z; qf[4 * j + 3] = qd.w;
        }
        float4 vv = *(const float4*)(sl + 512 + warp * 8 + cg * 4);
        const float eg = sl[576];
        const float bet = sl[577];

        const float Dn = eg * Dcur;                  // decay folded into scalar
        const float invDn = __fdividef(1.0f, Dn);
        const float bi = bet * invDn;

        // phase 1: kvs = k . Shat  (true kv_post_decay = Dn * kvs)
        ull kv2a = 0ull, kv2b = 0ull;
#pragma unroll
        for (int r = 0; r < 16; r++) {
            ull k2 = pack2(kf[r], kf[r]);
            kv2a = fma2(k2, S[r][0], kv2a);
            kv2b = fma2(k2, S[r][1], kv2b);
        }
#pragma unroll
        for (int mask = 2; mask <= 16; mask <<= 1) {
            kv2a = add2(kv2a, __shfl_xor_sync(0xffffffffu, kv2a, mask));
            kv2b = add2(kv2b, __shfl_xor_sync(0xffffffffu, kv2b, mask));
        }
        float kv0, kv1, kv2f, kv3;
        unpack2(kv2a, kv0, kv1);
        unpack2(kv2b, kv2f, kv3);

        // u' = (v - Dn*kvs) * beta / Dn
        ull u2a = pack2((vv.x - Dn * kv0) * bi, (vv.y - Dn * kv1) * bi);
        ull u2b = pack2((vv.z - Dn * kv2f) * bi, (vv.w - Dn * kv3) * bi);

        // phase 2: Shat += k (x) u' ; o = Dn * (q . Shat)
        ull o2a = 0ull, o2b = 0ull;
#pragma unroll
        for (int r = 0; r < 16; r++) {
            ull k2 = pack2(kf[r], kf[r]);
            ull q2 = pack2(qf[r], qf[r]);
            S[r][0] = fma2(k2, u2a, S[r][0]);
            o2a = fma2(q2, S[r][0], o2a);
            S[r][1] = fma2(k2, u2b, S[r][1]);
            o2b = fma2(q2, S[r][1], o2b);
        }
#pragma unroll
        for (int mask = 2; mask <= 16; mask <<= 1) {
            o2a = add2(o2a, __shfl_xor_sync(0xffffffffu, o2a, mask));
            o2b = add2(o2b, __shfl_xor_sync(0xffffffffu, o2b, mask));
        }
        if (rg == 0) {
            float4 o4;
            unpack2(o2a, o4.x, o4.y);
            unpack2(o2b, o4.z, o4.w);
            o4.x *= Dn; o4.y *= Dn; o4.z *= Dn; o4.w *= Dn;
            *(float4*)(Ob + (size_t)(bt0 + t) * VD) = o4;
        }

        Dcur = Dn;
        if (Dcur < 1e-18f) {     // uniform branch; rescale Shat back to true scale
            const ull d2 = pack2(Dcur, Dcur);
#pragma unroll
            for (int r = 0; r < 16; r++) {
                S[r][0] = mul2(S[r][0], d2);
                S[r][1] = mul2(S[r][1], d2);
            }
            Dcur = 1.0f;
        }
    };

    // prime slots 0..4 (groups carry data 0..4, one commit each)
#pragma unroll
    for (int p = 0; p < 5; p++) { issue(p, p); CP_COMMIT(); }

    for (int t = 0; t < T_; t += 2) {
        CP_WAIT3();           // data t and t+1 complete (<=3 newer groups outstanding)
        __syncthreads();      // all warps past reads of slots (t+5)&7,(t+6)&7 from 8 ago

        if (t + 5 < T_) issue((t + 5) & 7, t + 5);
        CP_COMMIT();
        step(t);

        if (t + 6 < T_) issue((t + 6) & 7, t + 6);
        CP_COMMIT();
        step(t + 1);
    }
}

// ---------------- gated RMSNorm + bf16 hi/lo split (fused) ----------------
__global__ __launch_bounds__(256) void normgate_kernel(const float* __restrict__ w) {
    const int bt = blockIdx.x;
    const int h = blockIdx.y;
    const int tid = threadIdx.x;
    const size_t obase = (size_t)bt * VD + h * DV;
    const size_t gbase = (size_t)bt * PST + GOFF + h * DV;
    float o0 = d_O[obase + tid];
    float o1 = d_O[obase + tid + 256];
    float ss = o0 * o0 + o1 * o1;
    __shared__ float red[8];
#pragma unroll
    for (int m = 16; m > 0; m >>= 1) ss += __shfl_xor_sync(0xffffffffu, ss, m);
    if ((tid & 31) == 0) red[tid >> 5] = ss;
    __syncthreads();
    float tot = 0.0f;
#pragma unroll
    for (int i = 0; i < 8; i++) tot += red[i];
    float rms = rsqrtf(tot * (1.0f / (float)DV) + 1e-5f);
    float g0 = d_P[gbase + tid];
    float g1 = d_P[gbase + tid + 256];
    float r0 = o0 * rms * w[tid]       * g0 * sigm(g0);
    float r1 = o1 * rms * w[tid + 256] * g1 * sigm(g1);
    // fused bf16 hi/lo split
    uint32_t hp = pkbf(r0, r1);
    float h0 = __uint_as_float(hp << 16);
    float h1 = __uint_as_float(hp & 0xffff0000u);
    uint32_t lp = pkbf(r0 - h0, r1 - h1);
    d_Gh[obase + tid]       = __ushort_as_bfloat16((unsigned short)(hp & 0xffff));
    d_Gh[obase + tid + 256] = __ushort_as_bfloat16((unsigned short)(hp >> 16));
    d_Gl[obase + tid]       = __ushort_as_bfloat16((unsigned short)(lp & 0xffff));
    d_Gl[obase + tid + 256] = __ushort_as_bfloat16((unsigned short)(lp >> 16));
}

// ---------------- streams/events (created once at static init) ----------------
struct GdnStreams {
    cudaStream_t s1, s2;
    cudaEvent_t evRoot, evW1, evW2, evWo, evGB, evP, evK, evV;
    GdnStreams() {
        cudaStreamCreateWithFlags(&s1, cudaStreamNonBlocking);
        cudaStreamCreateWithFlags(&s2, cudaStreamNonBlocking);
        cudaEventCreateWithFlags(&evRoot, cudaEventDisableTiming);
        cudaEventCreateWithFlags(&evW1, cudaEventDisableTiming);
        cudaEventCreateWithFlags(&evW2, cudaEventDisableTiming);
        cudaEventCreateWithFlags(&evWo, cudaEventDisableTiming);
        cudaEventCreateWithFlags(&evGB, cudaEventDisableTiming);
        cudaEventCreateWithFlags(&evP, cudaEventDisableTiming);
        cudaEventCreateWithFlags(&evK, cudaEventDisableTiming);
        cudaEventCreateWithFlags(&evV, cudaEventDisableTiming);
    }
};
static GdnStreams g_s;

// ---------------- host launcher ----------------
extern "C" void kernel_launch(void* const* d_in, const int* in_sizes, int n_in,
                              void* d_out, int out_size) {
    const float* H       = (const float*)d_in[0];
    const float* Wq      = (const float*)d_in[1];
    const float* Wk      = (const float*)d_in[2];
    const float* Wv      = (const float*)d_in[3];
    const float* Wa      = (const float*)d_in[4];
    const float* Wb      = (const float*)d_in[5];
    const float* Wg      = (const float*)d_in[6];
    const float* Wo      = (const float*)d_in[7];
    const float* conv_q  = (const float*)d_in[8];
    const float* conv_k  = (const float*)d_in[9];
    const float* conv_v  = (const float*)d_in[10];
    const float* A_log   = (const float*)d_in[11];
    const float* dt_bias = (const float*)d_in[12];
    const float* onw     = (const float*)d_in[13];

    float *pp, *qc, *kc;
    cudaGetSymbolAddress((void**)&pp, d_P);
    cudaGetSymbolAddress((void**)&qc, d_Qc);
    cudaGetSymbolAddress((void**)&kc, d_Kc);

    __nv_bfloat16 *hh, *hl, *wbh, *wbl, *woh, *wol, *gh, *gl;
    cudaGetSymbolAddress((void**)&hh, d_Hh);   cudaGetSymbolAddress((void**)&hl, d_Hl);
    cudaGetSymbolAddress((void**)&wbh, d_Wbh); cudaGetSymbolAddress((void**)&wbl, d_Wbl);
    cudaGetSymbolAddress((void**)&woh, d_Woh); cudaGetSymbolAddress((void**)&wol, d_Wol);
    cudaGetSymbolAddress((void**)&gh, d_Gh);   cudaGetSymbolAddress((void**)&gl, d_Gl);

    cudaFuncSetAttribute(gemm_bf, cudaFuncAttributeMaxDynamicSharedMemorySize, SMEM_GB);

    cudaStream_t s0 = 0;
    cudaStream_t s1 = g_s.s1, s2 = g_s.s2;

    // ---- fork: root event on origin stream so side streams join the capture ----
    cudaEventRecord(g_s.evRoot, s0);
    cudaStreamWaitEvent(s1, g_s.evRoot, 0);
    cudaStreamWaitEvent(s2, g_s.evRoot, 0);

    // s0: split H
    {
        int n4 = (BT * HID) / 4;
        split_kernel<<<(n4 + 255) / 256, 256, 0, s0>>>((const float4*)H, (uint2*)hh, (uint2*)hl, n4);
    }
    // s1: Wq/Wk/Wv splits into concatenated buffer
    {
        int n4q = (HID * KD) / 4;
        splitWs_kernel<<<(n4q + 255) / 256, 256, 0, s1>>>((const float4*)Wq, wbh, wbl, n4q, KD / 4, QOFF);
        splitWs_kernel<<<(n4q + 255) / 256, 256, 0, s1>>>((const float4*)Wk, wbh, wbl, n4q, KD / 4, KOFF);
        int n4v = (HID * VD) / 4;
        splitWs_kernel<<<(n4v + 255) / 256, 256, 0, s1>>>((const float4*)Wv, wbh, wbl, n4v, VD / 4, VOFF);
        cudaEventRecord(g_s.evW1, s1);
    }
    // s2: Wg split + Wo split + gate projections
    {
        int n4v = (HID * VD) / 4;
        splitWs_kernel<<<(n4v + 255) / 256, 256, 0, s2>>>((const float4*)Wg, wbh, wbl, n4v, VD / 4, GOFF);
        cudaEventRecord(g_s.evW2, s2);
        int n4o = (VD * HID) / 4;
        split_kernel<<<(n4o + 255) / 256, 256, 0, s2>>>((const float4*)Wo, (uint2*)woh, (uint2*)wol, n4o);
        cudaEventRecord(g_s.evWo, s2);
        gate_kernel<<<BT, 256, 0, s2>>>(H, Wa, Wb, A_log, dt_bias);
        cudaEventRecord(g_s.evGB, s2);
    }

    // ---- ONE fused projection GEMM: [4096 x 9216] ----
    cudaStreamWaitEvent(s0, g_s.evW1, 0);
    cudaStreamWaitEvent(s0, g_s.evW2, 0);
    gemm_bf<<<dim3(PST / BN, BT / BM), 256, SMEM_GB, s0>>>(hh, hl, wbh, wbl, pp, BT, PST, HID);
    cudaEventRecord(g_s.evP, s0);

    // ---- convs (3-way concurrent) ----
    convqk_kernel<<<dim3(BT, NH), 256, 0, s0>>>(pp, conv_q, qc, 0.0625f, QOFF);
    cudaStreamWaitEvent(s1, g_s.evP, 0);
    convqk_kernel<<<dim3(BT, NH), 256, 0, s1>>>(pp, conv_k, kc, 1.0f, KOFF);
    cudaEventRecord(g_s.evK, s1);
    cudaStreamWaitEvent(s2, g_s.evP, 0);
    convv_kernel<<<dim3(BT, VD / 256), 256, 0, s2>>>(pp, conv_v);
    cudaEventRecord(g_s.evV, s2);

    // ---- recurrence ----
    cudaStreamWaitEvent(s0, g_s.evK, 0);
    cudaStreamWaitEvent(s0, g_s.evV, 0);
    cudaStreamWaitEvent(s0, g_s.evGB, 0);
    recur_kernel<<<96, 256, 0, s0>>>();

    // ---- epilogue: fused normgate+split, then Wo GEMM ----
    normgate_kernel<<<dim3(BT, NH), 256, 0, s0>>>(onw);
    cudaStreamWaitEvent(s0, g_s.evWo, 0);
    gemm_bf<<<dim3(HID / BN, BT / BM), 256, SMEM_GB, s0>>>(gh, gl, woh, wol, (float*)d_out, BT, HID, VD);
}